// round 8
// baseline (speedup 1.0000x reference)
#include <cuda_runtime.h>

// CRF forward (log partition) on GB300.
// One 32-thread CTA per batch element; lane i owns tag i.
// Log-domain recurrence kept in base-2 with a lag-2 uniform shift so the
// per-step critical path has NO ex2/lg2/shuffle on it:
//   p_j        = acc_j * sc_j              (sc computed last iteration)
//   acc_i      = sum_j E[i][j] * p_j       (16x fma.rn.f32x2, E in regs)
//   la_i       = m_t + log2(acc_i) + el_i  (off-path, feeds lag-2 shift)
//   sc_j(next) = 2^( el_j + m_t - m_{t+1} ) (off-path)

#define T_TAGS 32
#define START_TAG 30
#define STOP_TAG 31
#define LOG2E 1.4426950408889634f
#define LN2   0.6931471805599453f
#define PF 8   // emission prefetch depth (register pipeline)

__device__ __forceinline__ float ex2a(float x) {
    float r; asm("ex2.approx.f32 %0, %1;" : "=f"(r) : "f"(x)); return r;
}
__device__ __forceinline__ float lg2a(float x) {
    float r; asm("lg2.approx.f32 %0, %1;" : "=f"(r) : "f"(x)); return r;
}
__device__ __forceinline__ unsigned long long pk2(float lo, float hi) {
    unsigned long long r;
    asm("mov.b64 %0, {%1, %2};" : "=l"(r) : "f"(lo), "f"(hi));
    return r;
}
__device__ __forceinline__ void upk2(unsigned long long v, float& lo, float& hi) {
    asm("mov.b64 {%0, %1}, %2;" : "=f"(lo), "=f"(hi) : "l"(v));
}
__device__ __forceinline__ unsigned long long fma2(unsigned long long a,
                                                   unsigned long long b,
                                                   unsigned long long c) {
    unsigned long long d;
    asm("fma.rn.f32x2 %0, %1, %2, %3;" : "=l"(d) : "l"(a), "l"(b), "l"(c));
    return d;
}
__device__ __forceinline__ unsigned long long add2(unsigned long long a,
                                                   unsigned long long b) {
    unsigned long long d;
    asm("add.rn.f32x2 %0, %1, %2;" : "=l"(d) : "l"(a), "l"(b));
    return d;
}

template <int SC>
__global__ __launch_bounds__(32, 16)
void crf_fwd_kernel(const float* __restrict__ feats,
                    const float* __restrict__ trans,
                    float* __restrict__ out,
                    int S_rt) {
    const int S = (SC > 0) ? SC : S_rt;
    const int lane = threadIdx.x;
    const int b = blockIdx.x;

    __shared__ __align__(16) float sp[2][T_TAGS];

    // ---- Load transition row i=lane, build E[i][j] = exp(trans[i][j]) packed in f32x2 pairs ----
    unsigned long long e2[16];
    {
        const float4* tr = reinterpret_cast<const float4*>(trans + lane * T_TAGS);
        #pragma unroll
        for (int k = 0; k < 8; k++) {
            float4 t = tr[k];
            float a0 = ex2a(t.x * LOG2E);
            float a1 = ex2a(t.y * LOG2E);
            float a2 = ex2a(t.z * LOG2E);
            float a3 = ex2a(t.w * LOG2E);
            e2[2 * k]     = pk2(a0, a1);
            e2[2 * k + 1] = pk2(a2, a3);
        }
    }
    // STOP-row transition score for this lane (log2 units), for termination
    const float t2stop = trans[STOP_TAG * T_TAGS + lane] * LOG2E;

    // ---- Emission register pipeline (PF deep) ----
    const float* f = feats + (size_t)b * (size_t)S * T_TAGS + lane;
    float ebuf[PF];
    #pragma unroll
    for (int k = 0; k < PF; k++) ebuf[k] = f[(size_t)k * T_TAGS];

    // ---- Step t=1 (closed form): alpha0 = -1e4 except START=0, so
    //      acc1_i = E[i][START] exactly in fp32. ----
    float acc;
    {
        float lo, hi;
        upk2(e2[START_TAG / 2], lo, hi);  // pair 15 = (E[i][30], E[i][31])
        acc = lo;                          // E[i][START_TAG]
    }
    float el = ebuf[0] * LOG2E;
    if (PF < S) ebuf[0] = f[(size_t)PF * T_TAGS];
    float lg = lg2a(acc);
    float lael = lg + el;                              // la^1 = m_1(=0) + lael
    float bc = __shfl_sync(0xffffffffu, lael, 0);      // la^1_{lane0}
    float m_cur = bc;                                  // m_2 = la^1_0
    float m_nxt = bc;                                  // m_3 = la^1_0
    float sc = ex2a(el - bc);                          // sc^1 = 2^{el1 + m1 - m2}
    float m_used = 0.0f;                               // m of last completed step

    // ---- Main recurrence, t = 2..S ----
    #pragma unroll 8
    for (int t = 2; t <= S; t++) {
        // critical path starts:
        float p = acc * sc;                 // p^t_j = 2^{la^{t-1}_j - m_t}
        sp[t & 1][lane] = p;
        __syncthreads();                    // 1-warp CTA: ~3-cycle BAR, drains STS

        const ulonglong2* q = reinterpret_cast<const ulonglong2*>(sp[t & 1]);
        unsigned long long aA = 0ull, aB = 0ull;
        #pragma unroll
        for (int k = 0; k < 8; k++) {
            ulonglong2 pv = q[k];           // (p[4k],p[4k+1]) , (p[4k+2],p[4k+3])
            aA = fma2(e2[2 * k],     pv.x, aA);
            aB = fma2(e2[2 * k + 1], pv.y, aB);
        }
        unsigned long long aT = add2(aA, aB);
        float lo, hi;
        upk2(aT, lo, hi);
        acc = lo + hi;                      // acc^t_i  (critical path ends)

        // ---- off-critical-path bookkeeping for t+1 / t+2 ----
        lg = lg2a(acc);
        float em = ebuf[(t - 1) & (PF - 1)];
        if (t - 1 + PF < S) ebuf[(t - 1) & (PF - 1)] = f[(size_t)(t - 1 + PF) * T_TAGS];
        el = em * LOG2E;
        lael = lg + el;                                 // la^t = m_t + lael
        bc = __shfl_sync(0xffffffffu, lael, 0);         // lg^t_0 + el^t_0
        float m_t2 = m_cur + bc;                        // m_{t+2} = la^t_0
        sc = ex2a(el + (m_cur - m_nxt));                // sc^t for p^{t+1}
        m_used = m_cur;
        m_cur = m_nxt;
        m_nxt = m_t2;
    }

    // ---- Termination: logZ = ln2 * log2sum2_j( la_j + T2[STOP][j] ) ----
    float v = m_used + lael + t2stop;  // log2 units; START lane = -inf (contributes 0)
    float vm = v;
    #pragma unroll
    for (int off = 16; off; off >>= 1)
        vm = fmaxf(vm, __shfl_xor_sync(0xffffffffu, vm, off));
    float ex = ex2a(v - vm);           // ex2a(-inf) = 0
    #pragma unroll
    for (int off = 16; off; off >>= 1)
        ex += __shfl_xor_sync(0xffffffffu, ex, off);
    if (lane == 0) out[b] = (vm + lg2a(ex)) * LN2;
}

extern "C" void kernel_launch(void* const* d_in, const int* in_sizes, int n_in,
                              void* d_out, int out_size) {
    const float* feats = (const float*)d_in[0];   // [B, S, 32]
    const float* trans = (const float*)d_in[1];   // [32, 32]
    float* out = (float*)d_out;                   // [B]

    const int B = out_size;
    const int S = in_sizes[0] / (B * T_TAGS);

    if (S == 512) {
        crf_fwd_kernel<512><<<B, 32>>>(feats, trans, out, S);
    } else {
        crf_fwd_kernel<0><<<B, 32>>>(feats, trans, out, S);
    }
}